// round 3
// baseline (speedup 1.0000x reference)
#include <cuda_runtime.h>
#include <cuda_bf16.h>
#include <math.h>

// Problem constants (fixed for this problem instance)
#define B_      8
#define S_      4096
#define HID_    2048
#define ADAPT_  32
#define RANK_   16
#define ACTIVE_ 8
#define SPLITS  32
#define ROWS_PER_SPLIT (S_ / SPLITS)   // 128

// Scratch (no allocation allowed -> device globals)
__device__ float g_partial[SPLITS * B_ * HID_];  // 2 MiB
__device__ float g_pooled [B_ * HID_];           // 64 KiB (mean, division folded in)
__device__ float g_sv     [B_ * RANK_];          // per-(b,r) scale: mask*rank_scales/32

// ---------------------------------------------------------------------------
// Kernel 1: partial sums over S (split into SPLITS chunks) — the 256 MiB read.
// grid (HID_/1024, B_, SPLITS) = 512 blocks, 256 threads. Each thread owns 4 h
// via float4. Warp reads 512B contiguous per LDG.128 -> perfect coalescing.
// 16 independent loads in flight per thread (unroll 4 x 4 rows) for high MLP.
// All blocks resident in one wave (131k threads << 303k capacity).
// ---------------------------------------------------------------------------
__global__ __launch_bounds__(256) void pool_partial_kernel(const float* __restrict__ hs)
{
    const int hbase = blockIdx.x * 1024 + threadIdx.x * 4;
    const int b = blockIdx.y;
    const int z = blockIdx.z;
    const float4* p = reinterpret_cast<const float4*>(
        hs + ((size_t)b * S_ + (size_t)z * ROWS_PER_SPLIT) * HID_ + hbase);
    const int stride4 = HID_ / 4;  // 512 float4 per row

    float4 a0 = make_float4(0.f, 0.f, 0.f, 0.f);
    float4 a1 = make_float4(0.f, 0.f, 0.f, 0.f);
    float4 a2 = make_float4(0.f, 0.f, 0.f, 0.f);
    float4 a3 = make_float4(0.f, 0.f, 0.f, 0.f);
    #pragma unroll 4
    for (int s = 0; s < ROWS_PER_SPLIT; s += 4) {
        float4 r0 = p[(s + 0) * stride4];
        float4 r1 = p[(s + 1) * stride4];
        float4 r2 = p[(s + 2) * stride4];
        float4 r3 = p[(s + 3) * stride4];
        a0.x += r0.x; a0.y += r0.y; a0.z += r0.z; a0.w += r0.w;
        a1.x += r1.x; a1.y += r1.y; a1.z += r1.z; a1.w += r1.w;
        a2.x += r2.x; a2.y += r2.y; a2.z += r2.z; a2.w += r2.w;
        a3.x += r3.x; a3.y += r3.y; a3.z += r3.z; a3.w += r3.w;
    }
    float4 acc;
    acc.x = (a0.x + a1.x) + (a2.x + a3.x);
    acc.y = (a0.y + a1.y) + (a2.y + a3.y);
    acc.z = (a0.z + a1.z) + (a2.z + a3.z);
    acc.w = (a0.w + a1.w) + (a2.w + a3.w);
    *reinterpret_cast<float4*>(g_partial + ((size_t)z * B_ + b) * HID_ + hbase) = acc;
}

// ---------------------------------------------------------------------------
// Kernel 2: reduce SPLITS partials -> pooled mean.
// 64 blocks x 256 threads: one scalar element per thread, 32 z-slices each.
// Spreads the 2 MiB L2-resident read over 64 SMs (LSU-issue floor binds at
// fewer blocks).
// ---------------------------------------------------------------------------
__global__ __launch_bounds__(256) void pool_reduce_kernel()
{
    const int i = blockIdx.x * 256 + threadIdx.x;  // < B_*HID_ = 16384
    float acc = 0.f;
    #pragma unroll
    for (int z = 0; z < SPLITS; ++z)
        acc += g_partial[(size_t)z * (B_ * HID_) + i];
    g_pooled[i] = acc * (1.0f / (float)S_);
}

// ---------------------------------------------------------------------------
// Kernel 3: tiny controller MLP + LayerNorm + exact GELU + top-8 mask.
// Single block, 1024 threads. Warp w handles (batch b = w/4, h-quarter q = w%4).
// ---------------------------------------------------------------------------
__global__ __launch_bounds__(1024) void mlp_mask_kernel(
    const float* __restrict__ W1, const float* __restrict__ b1,
    const float* __restrict__ ln_gamma, const float* __restrict__ ln_beta,
    const float* __restrict__ W2, const float* __restrict__ b2,
    const float* __restrict__ mask_logits, const float* __restrict__ rank_scales)
{
    __shared__ float xpart[B_][4][ADAPT_];
    __shared__ float xs[B_][ADAPT_];
    __shared__ float ls[B_][RANK_];

    const int t = threadIdx.x;
    const int w = t >> 5, lane = t & 31;
    const int b = w >> 2, q = w & 3;

    // x = pooled @ W1  (each warp: 512 of the 2048 h for one batch; lane = adapt col)
    {
        const float* pr  = g_pooled + b * HID_ + q * 512;
        const float* w1p = W1 + (size_t)(q * 512) * ADAPT_ + lane;
        float c0 = 0.f, c1 = 0.f, c2 = 0.f, c3 = 0.f;
        #pragma unroll 4
        for (int h = 0; h < 512; h += 4) {
            c0 += pr[h + 0] * w1p[(h + 0) * ADAPT_];
            c1 += pr[h + 1] * w1p[(h + 1) * ADAPT_];
            c2 += pr[h + 2] * w1p[(h + 2) * ADAPT_];
            c3 += pr[h + 3] * w1p[(h + 3) * ADAPT_];
        }
        xpart[b][q][lane] = (c0 + c1) + (c2 + c3);
    }
    __syncthreads();

    // LN + exact GELU: first 8 warps, one per batch, lane = adapt index j
    if (w < 8) {
        const int bb = w;
        float x = xpart[bb][0][lane] + xpart[bb][1][lane]
                + xpart[bb][2][lane] + xpart[bb][3][lane] + b1[lane];
        float s = x;
        #pragma unroll
        for (int off = 16; off; off >>= 1) s += __shfl_xor_sync(0xffffffffu, s, off);
        const float mu = s * (1.0f / 32.0f);
        const float d = x - mu;
        float v = d * d;
        #pragma unroll
        for (int off = 16; off; off >>= 1) v += __shfl_xor_sync(0xffffffffu, v, off);
        const float var = v * (1.0f / 32.0f);
        x = d * rsqrtf(var + 1e-5f) * ln_gamma[lane] + ln_beta[lane];
        x = 0.5f * x * (1.0f + erff(x * 0.70710678118654752440f));
        xs[bb][lane] = x;
    }
    __syncthreads();

    // logits = x @ W2 + b2 + mask_logits   (128 threads: b x r)
    if (t < B_ * RANK_) {
        const int bb = t >> 4, r = t & 15;
        float acc = b2[r] + mask_logits[r];
        #pragma unroll
        for (int j = 0; j < ADAPT_; ++j) acc += xs[bb][j] * W2[j * RANK_ + r];
        ls[bb][r] = acc;
    }
    __syncthreads();

    // top-8 selection with lax.top_k tie-break (earlier index wins ties)
    if (t < B_ * RANK_) {
        const int bb = t >> 4, r = t & 15;
        const float v = ls[bb][r];
        int cnt = 0;
        #pragma unroll
        for (int rp = 0; rp < RANK_; ++rp) {
            const float u = ls[bb][rp];
            cnt += (u > v) || (u == v && rp < r);
        }
        // fold the global 1/32 Hadamard normalization into the scale vector
        g_sv[bb * RANK_ + r] = (cnt < ACTIVE_) ? rank_scales[r] * (1.0f / 32.0f) : 0.0f;
    }
}

// ---------------------------------------------------------------------------
// Kernel 4: out[b,s,:] = FWHT16( rank_act[b,s,:] * sv[b,:] )
// H[d][r] = (-1)^popc(d&r) / 32 (the /32 is folded into sv).
// One thread per token; 4x float4 in, 4x float4 out. sv is 64B (one cache
// line) per batch and warp-uniform -> __ldg broadcast, no smem/barrier needed.
// ---------------------------------------------------------------------------
__global__ __launch_bounds__(256) void hadamard_kernel(
    const float* __restrict__ ra, float* __restrict__ out)
{
    // 4096 tokens / 256 threads = 16 blocks per batch -> b = blockIdx.x >> 4
    const float* sv = g_sv + (blockIdx.x >> 4) * RANK_;
    const float4 s0 = __ldg((const float4*)(sv + 0));
    const float4 s1 = __ldg((const float4*)(sv + 4));
    const float4 s2 = __ldg((const float4*)(sv + 8));
    const float4 s3 = __ldg((const float4*)(sv + 12));

    const size_t token = (size_t)blockIdx.x * 256 + threadIdx.x;  // < 32768
    const float4* p = reinterpret_cast<const float4*>(ra + token * RANK_);
    float4 i0 = p[0], i1 = p[1], i2 = p[2], i3 = p[3];

    float v[16];
    v[ 0] = i0.x * s0.x; v[ 1] = i0.y * s0.y; v[ 2] = i0.z * s0.z; v[ 3] = i0.w * s0.w;
    v[ 4] = i1.x * s1.x; v[ 5] = i1.y * s1.y; v[ 6] = i1.z * s1.z; v[ 7] = i1.w * s1.w;
    v[ 8] = i2.x * s2.x; v[ 9] = i2.y * s2.y; v[10] = i2.z * s2.z; v[11] = i2.w * s2.w;
    v[12] = i3.x * s3.x; v[13] = i3.y * s3.y; v[14] = i3.z * s3.z; v[15] = i3.w * s3.w;

    // 4-stage fast Walsh-Hadamard transform (natural/Sylvester order)
    #pragma unroll
    for (int len = 1; len < 16; len <<= 1) {
        #pragma unroll
        for (int i = 0; i < 16; ++i) {
            if (!(i & len)) {
                const float a = v[i], c = v[i | len];
                v[i] = a + c;
                v[i | len] = a - c;
            }
        }
    }

    float4* o = reinterpret_cast<float4*>(out + token * RANK_);
    o[0] = make_float4(v[ 0], v[ 1], v[ 2], v[ 3]);
    o[1] = make_float4(v[ 4], v[ 5], v[ 6], v[ 7]);
    o[2] = make_float4(v[ 8], v[ 9], v[10], v[11]);
    o[3] = make_float4(v[12], v[13], v[14], v[15]);
}

// ---------------------------------------------------------------------------
// Inputs (metadata order): hidden_states, rank_activations, W1, b1,
//   ln_gamma, ln_beta, W2, b2, mask_logits, rank_scales
// Output: float32 [8, 4096, 16]
// ---------------------------------------------------------------------------
extern "C" void kernel_launch(void* const* d_in, const int* in_sizes, int n_in,
                              void* d_out, int out_size)
{
    const float* hidden_states    = (const float*)d_in[0];
    const float* rank_activations = (const float*)d_in[1];
    const float* W1          = (const float*)d_in[2];
    const float* b1          = (const float*)d_in[3];
    const float* ln_gamma    = (const float*)d_in[4];
    const float* ln_beta     = (const float*)d_in[5];
    const float* W2          = (const float*)d_in[6];
    const float* b2          = (const float*)d_in[7];
    const float* mask_logits = (const float*)d_in[8];
    const float* rank_scales = (const float*)d_in[9];
    float* out = (float*)d_out;

    dim3 g1(HID_ / 1024, B_, SPLITS);
    pool_partial_kernel<<<g1, 256>>>(hidden_states);
    pool_reduce_kernel<<<(B_ * HID_) / 256, 256>>>();
    mlp_mask_kernel<<<1, 1024>>>(W1, b1, ln_gamma, ln_beta, W2, b2,
                                 mask_logits, rank_scales);
    hadamard_kernel<<<(B_ * S_) / 256, 256>>>(rank_activations, out);
}

// round 6
// speedup vs baseline: 1.5215x; 1.5215x over previous
#include <cuda_runtime.h>
#include <cuda_bf16.h>
#include <math.h>

// Problem constants (fixed for this problem instance)
#define B_      8
#define S_      4096
#define HID_    2048
#define ADAPT_  32
#define RANK_   16
#define ACTIVE_ 8
#define SPLITS  64
#define ROWS_PER_SPLIT (S_ / SPLITS)   // 64
#define HCHUNKS 32
#define HCHUNK_ROWS (HID_ / HCHUNKS)   // 64

// Scratch (no allocation allowed -> device globals)
__device__ float g_partial[SPLITS * B_ * HID_];        // 4 MiB
__device__ float g_pooled [B_ * HID_];                 // 64 KiB
__device__ float g_xpart  [HCHUNKS * B_ * ADAPT_];     // 32 KiB (W1 matvec partials)
__device__ float g_sv     [B_ * RANK_];                // mask*rank_scales/32

// ---------------------------------------------------------------------------
// Kernel 1: partial sums over S — the 256 MiB read (the roofline kernel).
// grid (2, B_, SPLITS) = 1024 blocks, 256 threads -> 6.9 blocks/SM, ~1% tail.
// float4 loads, warp reads 512B contiguous, 16 loads in flight per thread.
// ---------------------------------------------------------------------------
__global__ __launch_bounds__(256) void pool_partial_kernel(const float* __restrict__ hs)
{
    const int hbase = blockIdx.x * 1024 + threadIdx.x * 4;
    const int b = blockIdx.y;
    const int z = blockIdx.z;
    const float4* p = reinterpret_cast<const float4*>(
        hs + ((size_t)b * S_ + (size_t)z * ROWS_PER_SPLIT) * HID_ + hbase);
    const int stride4 = HID_ / 4;  // 512 float4 per row

    float4 a0 = make_float4(0.f, 0.f, 0.f, 0.f);
    float4 a1 = make_float4(0.f, 0.f, 0.f, 0.f);
    float4 a2 = make_float4(0.f, 0.f, 0.f, 0.f);
    float4 a3 = make_float4(0.f, 0.f, 0.f, 0.f);
    #pragma unroll 4
    for (int s = 0; s < ROWS_PER_SPLIT; s += 4) {
        float4 r0 = p[(s + 0) * stride4];
        float4 r1 = p[(s + 1) * stride4];
        float4 r2 = p[(s + 2) * stride4];
        float4 r3 = p[(s + 3) * stride4];
        a0.x += r0.x; a0.y += r0.y; a0.z += r0.z; a0.w += r0.w;
        a1.x += r1.x; a1.y += r1.y; a1.z += r1.z; a1.w += r1.w;
        a2.x += r2.x; a2.y += r2.y; a2.z += r2.z; a2.w += r2.w;
        a3.x += r3.x; a3.y += r3.y; a3.z += r3.z; a3.w += r3.w;
    }
    float4 acc;
    acc.x = (a0.x + a1.x) + (a2.x + a3.x);
    acc.y = (a0.y + a1.y) + (a2.y + a3.y);
    acc.z = (a0.z + a1.z) + (a2.z + a3.z);
    acc.w = (a0.w + a1.w) + (a2.w + a3.w);
    *reinterpret_cast<float4*>(g_partial + ((size_t)z * B_ + b) * HID_ + hbase) = acc;
}

// ---------------------------------------------------------------------------
// Kernel 2: reduce SPLITS partials -> pooled mean.
// 64 blocks x 256 threads, one scalar element per thread, L2-resident reads.
// ---------------------------------------------------------------------------
__global__ __launch_bounds__(256) void pool_reduce_kernel()
{
    const int i = blockIdx.x * 256 + threadIdx.x;  // < B_*HID_ = 16384
    float acc = 0.f;
    #pragma unroll
    for (int z = 0; z < SPLITS; ++z)
        acc += g_partial[(size_t)z * (B_ * HID_) + i];
    g_pooled[i] = acc * (1.0f / (float)S_);
}

// ---------------------------------------------------------------------------
// Kernel 2b: W1 matvec partials, spread over 32 blocks (one 64-row h-chunk
// each) instead of living inside a single-SM block. Warp = batch, lane = adapt
// column. Each warp: 64 coalesced 128B W1 row reads (L1-shared across the 8
// warps of the block, which all read the same chunk).
// ---------------------------------------------------------------------------
__global__ __launch_bounds__(256) void w1_partial_kernel(const float* __restrict__ W1)
{
    const int t = threadIdx.x;
    const int b = t >> 5, j = t & 31;
    const int h0 = blockIdx.x * HCHUNK_ROWS;

    const float* pr  = g_pooled + b * HID_ + h0;
    const float* w1p = W1 + (size_t)h0 * ADAPT_ + j;
    float c0 = 0.f, c1 = 0.f, c2 = 0.f, c3 = 0.f;
    #pragma unroll
    for (int h = 0; h < HCHUNK_ROWS; h += 4) {
        c0 += pr[h + 0] * w1p[(h + 0) * ADAPT_];
        c1 += pr[h + 1] * w1p[(h + 1) * ADAPT_];
        c2 += pr[h + 2] * w1p[(h + 2) * ADAPT_];
        c3 += pr[h + 3] * w1p[(h + 3) * ADAPT_];
    }
    g_xpart[((size_t)blockIdx.x * B_ + b) * ADAPT_ + j] = (c0 + c1) + (c2 + c3);
}

// ---------------------------------------------------------------------------
// Kernel 3: reduce xpart + LayerNorm + exact GELU + W2 + top-8 mask.
// Single block, 256 threads — all inputs now tiny / L2-resident.
// Warp w = batch, lane = adapt index j.
// ---------------------------------------------------------------------------
__global__ __launch_bounds__(256) void mlp_mask_kernel(
    const float* __restrict__ b1,
    const float* __restrict__ ln_gamma, const float* __restrict__ ln_beta,
    const float* __restrict__ W2, const float* __restrict__ b2,
    const float* __restrict__ mask_logits, const float* __restrict__ rank_scales)
{
    __shared__ float xs[B_][ADAPT_];
    __shared__ float ls[B_][RANK_];

    const int t = threadIdx.x;
    const int w = t >> 5, lane = t & 31;

    // x[b][j] = sum over 32 chunks + b1; then LN + exact GELU
    {
        const int bb = w;  // 8 warps <-> 8 batches
        float x = 0.f;
        #pragma unroll
        for (int c = 0; c < HCHUNKS; ++c)
            x += g_xpart[((size_t)c * B_ + bb) * ADAPT_ + lane];
        x += b1[lane];

        float s = x;
        #pragma unroll
        for (int off = 16; off; off >>= 1) s += __shfl_xor_sync(0xffffffffu, s, off);
        const float mu = s * (1.0f / 32.0f);
        const float d = x - mu;
        float v = d * d;
        #pragma unroll
        for (int off = 16; off; off >>= 1) v += __shfl_xor_sync(0xffffffffu, v, off);
        const float var = v * (1.0f / 32.0f);
        x = d * rsqrtf(var + 1e-5f) * ln_gamma[lane] + ln_beta[lane];
        x = 0.5f * x * (1.0f + erff(x * 0.70710678118654752440f));
        xs[bb][lane] = x;
    }
    __syncthreads();

    // logits = x @ W2 + b2 + mask_logits   (128 threads: b x r)
    if (t < B_ * RANK_) {
        const int bb = t >> 4, r = t & 15;
        float acc = b2[r] + mask_logits[r];
        #pragma unroll
        for (int j = 0; j < ADAPT_; ++j) acc += xs[bb][j] * W2[j * RANK_ + r];
        ls[bb][r] = acc;
    }
    __syncthreads();

    // top-8 selection with lax.top_k tie-break (earlier index wins ties)
    if (t < B_ * RANK_) {
        const int bb = t >> 4, r = t & 15;
        const float v = ls[bb][r];
        int cnt = 0;
        #pragma unroll
        for (int rp = 0; rp < RANK_; ++rp) {
            const float u = ls[bb][rp];
            cnt += (u > v) || (u == v && rp < r);
        }
        // fold the global 1/32 Hadamard normalization into the scale vector
        g_sv[bb * RANK_ + r] = (cnt < ACTIVE_) ? rank_scales[r] * (1.0f / 32.0f) : 0.0f;
    }
}

// ---------------------------------------------------------------------------
// Kernel 4: out[b,s,:] = FWHT16( rank_act[b,s,:] * sv[b,:] )
// H[d][r] = (-1)^popc(d&r) / 32 (the /32 is folded into sv).
// 256 blocks x 128 threads (>=1 block/SM; 128 blocks measured 13% occ,
// 382 GB/s). sv is one 64B line per batch, warp-uniform -> L1 broadcast.
// ---------------------------------------------------------------------------
__global__ __launch_bounds__(128) void hadamard_kernel(
    const float* __restrict__ ra, float* __restrict__ out)
{
    // 4096 tokens / 128 threads = 32 blocks per batch -> b = blockIdx.x >> 5
    const float* sv = g_sv + (blockIdx.x >> 5) * RANK_;
    const float4 s0 = __ldg((const float4*)(sv + 0));
    const float4 s1 = __ldg((const float4*)(sv + 4));
    const float4 s2 = __ldg((const float4*)(sv + 8));
    const float4 s3 = __ldg((const float4*)(sv + 12));

    const size_t token = (size_t)blockIdx.x * 128 + threadIdx.x;  // < 32768
    const float4* p = reinterpret_cast<const float4*>(ra + token * RANK_);
    float4 i0 = p[0], i1 = p[1], i2 = p[2], i3 = p[3];

    float v[16];
    v[ 0] = i0.x * s0.x; v[ 1] = i0.y * s0.y; v[ 2] = i0.z * s0.z; v[ 3] = i0.w * s0.w;
    v[ 4] = i1.x * s1.x; v[ 5] = i1.y * s1.y; v[ 6] = i1.z * s1.z; v[ 7] = i1.w * s1.w;
    v[ 8] = i2.x * s2.x; v[ 9] = i2.y * s2.y; v[10] = i2.z * s2.z; v[11] = i2.w * s2.w;
    v[12] = i3.x * s3.x; v[13] = i3.y * s3.y; v[14] = i3.z * s3.z; v[15] = i3.w * s3.w;

    // 4-stage fast Walsh-Hadamard transform (natural/Sylvester order)
    #pragma unroll
    for (int len = 1; len < 16; len <<= 1) {
        #pragma unroll
        for (int i = 0; i < 16; ++i) {
            if (!(i & len)) {
                const float a = v[i], c = v[i | len];
                v[i] = a + c;
                v[i | len] = a - c;
            }
        }
    }

    float4* o = reinterpret_cast<float4*>(out + token * RANK_);
    o[0] = make_float4(v[ 0], v[ 1], v[ 2], v[ 3]);
    o[1] = make_float4(v[ 4], v[ 5], v[ 6], v[ 7]);
    o[2] = make_float4(v[ 8], v[ 9], v[10], v[11]);
    o[3] = make_float4(v[12], v[13], v[14], v[15]);
}

// ---------------------------------------------------------------------------
// Inputs (metadata order): hidden_states, rank_activations, W1, b1,
//   ln_gamma, ln_beta, W2, b2, mask_logits, rank_scales
// Output: float32 [8, 4096, 16]
// ---------------------------------------------------------------------------
extern "C" void kernel_launch(void* const* d_in, const int* in_sizes, int n_in,
                              void* d_out, int out_size)
{
    const float* hidden_states    = (const float*)d_in[0];
    const float* rank_activations = (const float*)d_in[1];
    const float* W1          = (const float*)d_in[2];
    const float* b1          = (const float*)d_in[3];
    const float* ln_gamma    = (const float*)d_in[4];
    const float* ln_beta     = (const float*)d_in[5];
    const float* W2          = (const float*)d_in[6];
    const float* b2          = (const float*)d_in[7];
    const float* mask_logits = (const float*)d_in[8];
    const float* rank_scales = (const float*)d_in[9];
    float* out = (float*)d_out;

    dim3 g1(HID_ / 1024, B_, SPLITS);
    pool_partial_kernel<<<g1, 256>>>(hidden_states);
    pool_reduce_kernel<<<(B_ * HID_) / 256, 256>>>();
    w1_partial_kernel<<<HCHUNKS, 256>>>(W1);
    mlp_mask_kernel<<<1, 256>>>(b1, ln_gamma, ln_beta, W2, b2,
                                mask_logits, rank_scales);
    hadamard_kernel<<<(B_ * S_) / 128, 128>>>(rank_activations, out);
}